// round 11
// baseline (speedup 1.0000x reference)
#include <cuda_runtime.h>
#include <cuda_fp16.h>
#include <cstdint>
#include <cstddef>

// ===========================================================================
// SelfAttention via mma.sync.m16n8k16, split-fp16 emulation.
//   G  = wk . wq^T   (unbatched, 3-pass)   } hh pass: fp32 acc
//   tT = xT . G      (batched, 3-pass)     } correction passes: fp16 acc,
//   kq = xT . tT /32 (batched, 3-pass)     }   folded into fp32 in epilogue
//   sm = softmax(kq) (1-digit)
//   u  = sm . xN     (batched, 1-pass, fp32 acc)
//   out= wvT . u     (batched, 1-pass, fp32 acc)
// 3-pass core: CTA 128x64, warp 32x32, BK=32, 2-stage double buffer.
// 1-pass core: CTA 128x128, warp 32x64, BK=32, 2-stage double buffer.
// ===========================================================================

#define L 1024
#define BATCH 16
#define PER_B ((size_t)L * L)
#define ELTS ((size_t)BATCH * L * L)

#define BK 32
#define PITCH 80                         // 64B data + 16B pad per 32-fp16 row

// ---- 3-pass core geometry (CTA 128x64) ----
#define A3_COMP (128 * PITCH)            // 10240
#define B3_COMP (64 * PITCH)             // 5120
#define OFF3_AH 0
#define OFF3_AL (A3_COMP)
#define OFF3_BH (2 * A3_COMP)
#define OFF3_BL (2 * A3_COMP + B3_COMP)
#define STAGE3_B (2 * A3_COMP + 2 * B3_COMP)   // 30720
#define SMEM3 (2 * STAGE3_B)                   // 61440

// ---- 1-pass core geometry (CTA 128x128) ----
#define A1_COMP (128 * PITCH)
#define OFF1_A 0
#define OFF1_B (A1_COMP)
#define STAGE1_B (2 * A1_COMP)                 // 20480
#define SMEM1 (2 * STAGE1_B)                   // 40960

#define W_PRESCALE 256.0f

// ---- scratch (device globals; cudaMalloc forbidden) ----
__device__ __align__(1024) __half g_xT_hi[ELTS], g_xT_lo[ELTS];
__device__ __align__(1024) __half g_xN_hi[ELTS];
__device__ __align__(1024) __half g_tT_hi[ELTS], g_tT_lo[ELTS];
__device__ __align__(1024) __half g_sm_hi[ELTS];
__device__ __align__(1024) __half g_u_hi[ELTS];
__device__ __align__(1024) __half g_G_hi[L * L], g_G_lo[L * L];
__device__ __align__(1024) __half g_wkN_hi[L * L], g_wkN_lo[L * L];
__device__ __align__(1024) __half g_wqN_hi[L * L], g_wqN_lo[L * L];
__device__ __align__(1024) __half g_wvT_hi[L * L];
__device__ __align__(1024) float g_kq[ELTS];

// ---------------------------------------------------------------------------
__device__ __forceinline__ uint32_t smem_u32(const void* p) {
    uint32_t a;
    asm("{ .reg .u64 t; cvta.to.shared.u64 t, %1; cvt.u32.u64 %0, t; }"
        : "=r"(a) : "l"(p));
    return a;
}

__device__ __forceinline__ void cp16(uint32_t dst, const void* src) {
    asm volatile("cp.async.cg.shared.global [%0], [%1], 16;"
                 :: "r"(dst), "l"(src) : "memory");
}
#define CP_COMMIT() asm volatile("cp.async.commit_group;" ::: "memory")
#define CP_WAIT(n)  asm volatile("cp.async.wait_group %0;" :: "n"(n) : "memory")

__device__ __forceinline__ void ldsm4(uint32_t* r, uint32_t addr) {
    asm volatile("ldmatrix.sync.aligned.m8n8.x4.shared.b16 {%0,%1,%2,%3}, [%4];"
                 : "=r"(r[0]), "=r"(r[1]), "=r"(r[2]), "=r"(r[3]) : "r"(addr));
}

// fp32-accumulator MMA
__device__ __forceinline__ void mma_f32(float* d, const uint32_t* a,
                                        uint32_t b0, uint32_t b1) {
    asm volatile(
        "mma.sync.aligned.m16n8k16.row.col.f32.f16.f16.f32 "
        "{%0,%1,%2,%3}, {%4,%5,%6,%7}, {%8,%9}, {%0,%1,%2,%3};"
        : "+f"(d[0]), "+f"(d[1]), "+f"(d[2]), "+f"(d[3])
        : "r"(a[0]), "r"(a[1]), "r"(a[2]), "r"(a[3]), "r"(b0), "r"(b1));
}

// fp16-accumulator MMA (half-rate-free path for correction terms)
__device__ __forceinline__ void mma_f16(uint32_t* d, const uint32_t* a,
                                        uint32_t b0, uint32_t b1) {
    asm volatile(
        "mma.sync.aligned.m16n8k16.row.col.f16.f16.f16.f16 "
        "{%0,%1}, {%2,%3,%4,%5}, {%6,%7}, {%0,%1};"
        : "+r"(d[0]), "+r"(d[1])
        : "r"(a[0]), "r"(a[1]), "r"(a[2]), "r"(a[3]), "r"(b0), "r"(b1));
}

// ---------------------------------------------------------------------------
// 3-pass core: D[i][j] = sum_k (Ah+Al)[i,k]*(Bh+Bl)[j,k] (lo*lo dropped).
// CTA 128x64, 256 threads: 4(M) x 2(N) warps, 32x32 warp tiles, BK=32.
// hh -> fp32 acc; al*bh and ah*bl -> one shared fp16 acc, folded at end.
// EPI 0: fp32*scale.  EPI 1: hi/lo fp16 split of acc*scale.
// ---------------------------------------------------------------------------
template <int EPI>
__device__ __forceinline__ void gemm3p(
    const __half* __restrict__ Ah, const __half* __restrict__ Al,
    const __half* __restrict__ Bh, const __half* __restrict__ Bl,
    float scale, float* __restrict__ outF,
    __half* __restrict__ outHi, __half* __restrict__ outLo)
{
    extern __shared__ char dyn[];
    const uint32_t sbase = smem_u32(dyn);

    const int tid  = threadIdx.x;
    const int wid  = tid >> 5;
    const int lane = tid & 31;
    const int wm   = wid & 3;            // 4 warps along M (32 rows)
    const int wn   = wid >> 2;           // 2 warps along N (32 cols)

    const int M0 = blockIdx.y * 128;
    const int N0 = blockIdx.x * 64;

    // cp.async: ci = tid&3 (16B chunk), rr = tid>>2 (0..63); 6 chunks/thread
    const int ci = tid & 3;
    const int rr = tid >> 2;
    const __half* gAh = Ah + (size_t)(M0 + rr) * L;
    const __half* gAl = Al + (size_t)(M0 + rr) * L;
    const __half* gBh = Bh + (size_t)(N0 + rr) * L;
    const __half* gBl = Bl + (size_t)(N0 + rr) * L;
    const uint32_t sO  = rr * PITCH + ci * 16;
    const uint32_t sO2 = (rr + 64) * PITCH + ci * 16;
    const size_t g2 = (size_t)64 * L;

    auto load_stage = [&](int stage, int kt) {
        const uint32_t sb = sbase + stage * STAGE3_B;
        const size_t   gk = (size_t)kt * BK + ci * 8;
        cp16(sb + OFF3_AH + sO,  gAh + gk);
        cp16(sb + OFF3_AH + sO2, gAh + g2 + gk);
        cp16(sb + OFF3_AL + sO,  gAl + gk);
        cp16(sb + OFF3_AL + sO2, gAl + g2 + gk);
        cp16(sb + OFF3_BH + sO,  gBh + gk);
        cp16(sb + OFF3_BL + sO,  gBl + gk);
    };

    load_stage(0, 0); CP_COMMIT();
    load_stage(1, 1); CP_COMMIT();

    const uint32_t lanePart = (uint32_t)((lane & 15) * PITCH + (lane >> 4) * 16);
    const uint32_t aOffH = OFF3_AH + (uint32_t)(wm * 32 * PITCH) + lanePart;
    const uint32_t aOffL = OFF3_AL + (uint32_t)(wm * 32 * PITCH) + lanePart;
    const uint32_t bOffH = OFF3_BH + (uint32_t)(wn * 32 * PITCH) + lanePart;
    const uint32_t bOffL = OFF3_BL + (uint32_t)(wn * 32 * PITCH) + lanePart;

    float    acc[2][4][4];               // hh, fp32
    uint32_t acc16[2][4][2];             // corrections, fp16x2
#pragma unroll
    for (int i = 0; i < 2; i++)
#pragma unroll
        for (int j = 0; j < 4; j++) {
#pragma unroll
            for (int k = 0; k < 4; k++) acc[i][j][k] = 0.0f;
            acc16[i][j][0] = 0u; acc16[i][j][1] = 0u;
        }

    const int NKT = L / BK;              // 32
    for (int kt = 0; kt < NKT; kt++) {
        CP_WAIT(1);
        __syncthreads();

        const uint32_t sb = sbase + (kt & 1) * STAGE3_B;
#pragma unroll
        for (int ks = 0; ks < 2; ks++) {
            const uint32_t ko = (uint32_t)(ks * 32);

            uint32_t ah[2][4], al[2][4];
#pragma unroll
            for (int tm = 0; tm < 2; tm++) {
                ldsm4(ah[tm], sb + aOffH + (uint32_t)(tm * 16 * PITCH) + ko);
                ldsm4(al[tm], sb + aOffL + (uint32_t)(tm * 16 * PITCH) + ko);
            }
            uint32_t bh[4][2];
            {
                uint32_t t0[4], t1[4];
                ldsm4(t0, sb + bOffH + ko);
                ldsm4(t1, sb + bOffH + (uint32_t)(16 * PITCH) + ko);
                bh[0][0] = t0[0]; bh[0][1] = t0[2];
                bh[1][0] = t0[1]; bh[1][1] = t0[3];
                bh[2][0] = t1[0]; bh[2][1] = t1[2];
                bh[3][0] = t1[1]; bh[3][1] = t1[3];
            }
            // pass 1: ah*bh -> fp32 acc
#pragma unroll
            for (int tm = 0; tm < 2; tm++)
#pragma unroll
                for (int tn = 0; tn < 4; tn++)
                    mma_f32(acc[tm][tn], ah[tm], bh[tn][0], bh[tn][1]);
            // pass 2: al*bh -> fp16 acc (bh dead after)
#pragma unroll
            for (int tm = 0; tm < 2; tm++)
#pragma unroll
                for (int tn = 0; tn < 4; tn++)
                    mma_f16(acc16[tm][tn], al[tm], bh[tn][0], bh[tn][1]);
            // pass 3: ah*bl -> fp16 acc
            uint32_t bl[4][2];
            {
                uint32_t t0[4], t1[4];
                ldsm4(t0, sb + bOffL + ko);
                ldsm4(t1, sb + bOffL + (uint32_t)(16 * PITCH) + ko);
                bl[0][0] = t0[0]; bl[0][1] = t0[2];
                bl[1][0] = t0[1]; bl[1][1] = t0[3];
                bl[2][0] = t1[0]; bl[2][1] = t1[2];
                bl[3][0] = t1[1]; bl[3][1] = t1[3];
            }
#pragma unroll
            for (int tm = 0; tm < 2; tm++)
#pragma unroll
                for (int tn = 0; tn < 4; tn++)
                    mma_f16(acc16[tm][tn], ah[tm], bl[tn][0], bl[tn][1]);
        }

        __syncthreads();
        if (kt + 2 < NKT) load_stage(kt & 1, kt + 2);
        CP_COMMIT();
    }

    // ---- epilogue: fold fp16 corrections, scale, store ----
    const int mBase = M0 + wm * 32 + (lane >> 2);
    const int cBase = N0 + wn * 32 + (lane & 3) * 2;
#pragma unroll
    for (int tm = 0; tm < 2; tm++)
#pragma unroll
        for (int tn = 0; tn < 4; tn++) {
            const float* a = acc[tm][tn];
            __half2 c01 = *reinterpret_cast<__half2*>(&acc16[tm][tn][0]);
            __half2 c23 = *reinterpret_cast<__half2*>(&acc16[tm][tn][1]);
            float f0 = (a[0] + __low2float(c01))  * scale;
            float f1 = (a[1] + __high2float(c01)) * scale;
            float f2 = (a[2] + __low2float(c23))  * scale;
            float f3 = (a[3] + __high2float(c23)) * scale;
            const int m = mBase + tm * 16;
            const int c = cBase + tn * 8;
            const size_t o0 = (size_t)m * L + c;
            const size_t o1 = o0 + 8 * L;
            if (EPI == 0) {
                *reinterpret_cast<float2*>(&outF[o0]) = make_float2(f0, f1);
                *reinterpret_cast<float2*>(&outF[o1]) = make_float2(f2, f3);
            } else {
                __half h0 = __float2half(f0), h1 = __float2half(f1);
                __half h2 = __float2half(f2), h3 = __float2half(f3);
                __half l0 = __float2half(f0 - __half2float(h0));
                __half l1 = __float2half(f1 - __half2float(h1));
                __half l2 = __float2half(f2 - __half2float(h2));
                __half l3 = __float2half(f3 - __half2float(h3));
                uint32_t hp0 = (uint32_t)__half_as_ushort(h0) |
                               ((uint32_t)__half_as_ushort(h1) << 16);
                uint32_t hp1 = (uint32_t)__half_as_ushort(h2) |
                               ((uint32_t)__half_as_ushort(h3) << 16);
                uint32_t lp0 = (uint32_t)__half_as_ushort(l0) |
                               ((uint32_t)__half_as_ushort(l1) << 16);
                uint32_t lp1 = (uint32_t)__half_as_ushort(l2) |
                               ((uint32_t)__half_as_ushort(l3) << 16);
                *reinterpret_cast<uint32_t*>(&outHi[o0]) = hp0;
                *reinterpret_cast<uint32_t*>(&outHi[o1]) = hp1;
                *reinterpret_cast<uint32_t*>(&outLo[o0]) = lp0;
                *reinterpret_cast<uint32_t*>(&outLo[o1]) = lp1;
            }
        }
}

// ---------------------------------------------------------------------------
// 1-pass core: D[i][j] = sum_k A[i,k]*B[j,k], fp32 acc.
// CTA 128x128, 256 threads: 4(M) x 2(N) warps, 32x64 warp tiles, BK=32.
// EPI 0: fp32*scale.  EPI 2: hi fp16 only.
// ---------------------------------------------------------------------------
template <int EPI>
__device__ __forceinline__ void gemm1p(
    const __half* __restrict__ A, const __half* __restrict__ B,
    float scale, float* __restrict__ outF, __half* __restrict__ outHi)
{
    extern __shared__ char dyn[];
    const uint32_t sbase = smem_u32(dyn);

    const int tid  = threadIdx.x;
    const int wid  = tid >> 5;
    const int lane = tid & 31;
    const int wm   = wid & 3;
    const int wn   = wid >> 2;

    const int M0 = blockIdx.y * 128;
    const int N0 = blockIdx.x * 128;

    const int ci = tid & 3;
    const int rr = tid >> 2;
    const __half* gA = A + (size_t)(M0 + rr) * L;
    const __half* gB = B + (size_t)(N0 + rr) * L;
    const uint32_t sO  = rr * PITCH + ci * 16;
    const uint32_t sO2 = (rr + 64) * PITCH + ci * 16;
    const size_t g2 = (size_t)64 * L;

    auto load_stage = [&](int stage, int kt) {
        const uint32_t sb = sbase + stage * STAGE1_B;
        const size_t   gk = (size_t)kt * BK + ci * 8;
        cp16(sb + OFF1_A + sO,  gA + gk);
        cp16(sb + OFF1_A + sO2, gA + g2 + gk);
        cp16(sb + OFF1_B + sO,  gB + gk);
        cp16(sb + OFF1_B + sO2, gB + g2 + gk);
    };

    load_stage(0, 0); CP_COMMIT();
    load_stage(1, 1); CP_COMMIT();

    const uint32_t lanePart = (uint32_t)((lane & 15) * PITCH + (lane >> 4) * 16);
    const uint32_t aOff = OFF1_A + (uint32_t)(wm * 32 * PITCH) + lanePart;
    const uint32_t bOff = OFF1_B + (uint32_t)(wn * 64 * PITCH) + lanePart;

    float acc[2][8][4];
#pragma unroll
    for (int i = 0; i < 2; i++)
#pragma unroll
        for (int j = 0; j < 8; j++)
#pragma unroll
            for (int k = 0; k < 4; k++) acc[i][j][k] = 0.0f;

    const int NKT = L / BK;
    for (int kt = 0; kt < NKT; kt++) {
        CP_WAIT(1);
        __syncthreads();

        const uint32_t sb = sbase + (kt & 1) * STAGE1_B;
#pragma unroll
        for (int ks = 0; ks < 2; ks++) {
            const uint32_t ko = (uint32_t)(ks * 32);
            uint32_t a[2][4];
#pragma unroll
            for (int tm = 0; tm < 2; tm++)
                ldsm4(a[tm], sb + aOff + (uint32_t)(tm * 16 * PITCH) + ko);
            uint32_t b[8][2];
#pragma unroll
            for (int g = 0; g < 4; g++) {
                uint32_t t[4];
                ldsm4(t, sb + bOff + (uint32_t)(g * 16 * PITCH) + ko);
                b[2 * g][0] = t[0];     b[2 * g][1] = t[2];
                b[2 * g + 1][0] = t[1]; b[2 * g + 1][1] = t[3];
            }
#pragma unroll
            for (int tm = 0; tm < 2; tm++)
#pragma unroll
                for (int tn = 0; tn < 8; tn++)
                    mma_f32(acc[tm][tn], a[tm], b[tn][0], b[tn][1]);
        }

        __syncthreads();
        if (kt + 2 < NKT) load_stage(kt & 1, kt + 2);
        CP_COMMIT();
    }

    const int mBase = M0 + wm * 32 + (lane >> 2);
    const int cBase = N0 + wn * 64 + (lane & 3) * 2;
#pragma unroll
    for (int tm = 0; tm < 2; tm++)
#pragma unroll
        for (int tn = 0; tn < 8; tn++) {
            const float* a = acc[tm][tn];
            const int m = mBase + tm * 16;
            const int c = cBase + tn * 8;
            const size_t o0 = (size_t)m * L + c;
            const size_t o1 = o0 + 8 * L;
            if (EPI == 0) {
                *reinterpret_cast<float2*>(&outF[o0]) =
                    make_float2(a[0] * scale, a[1] * scale);
                *reinterpret_cast<float2*>(&outF[o1]) =
                    make_float2(a[2] * scale, a[3] * scale);
            } else {
#pragma unroll
                for (int p = 0; p < 2; p++) {
                    const float v0 = a[2 * p] * scale, v1 = a[2 * p + 1] * scale;
                    uint32_t hp = (uint32_t)__half_as_ushort(__float2half(v0)) |
                                  ((uint32_t)__half_as_ushort(__float2half(v1)) << 16);
                    *reinterpret_cast<uint32_t*>(&outHi[p ? o1 : o0]) = hp;
                }
            }
        }
}

// ---------------------------------------------------------------------------
// kernels
// ---------------------------------------------------------------------------
__global__ void __launch_bounds__(256, 2)
g_kernel(const __half* __restrict__ WKNH, const __half* __restrict__ WKNL,
         const __half* __restrict__ WQNH, const __half* __restrict__ WQNL,
         __half* __restrict__ GH, __half* __restrict__ GL)
{
    gemm3p<1>(WKNH, WKNL, WQNH, WQNL, 1.0f / 4096.0f, nullptr, GH, GL);
}

__global__ void __launch_bounds__(256, 2)
t_kernel(const __half* __restrict__ XTH, const __half* __restrict__ XTL,
         const __half* __restrict__ GH, const __half* __restrict__ GL,
         __half* __restrict__ TTH, __half* __restrict__ TTL)
{
    const size_t bo = (size_t)blockIdx.z * PER_B;
    gemm3p<1>(XTH + bo, XTL + bo, GH, GL, 1.0f, nullptr, TTH + bo, TTL + bo);
}

__global__ void __launch_bounds__(256, 2)
kq_kernel(const __half* __restrict__ XTH, const __half* __restrict__ XTL,
          const __half* __restrict__ TTH, const __half* __restrict__ TTL,
          float* __restrict__ outF)
{
    const size_t bo = (size_t)blockIdx.z * PER_B;
    gemm3p<0>(XTH + bo, XTL + bo, TTH + bo, TTL + bo,
              1.0f / 512.0f, outF + bo, nullptr, nullptr);
}

__global__ void __launch_bounds__(256, 2)
u_kernel(const __half* __restrict__ SMH, const __half* __restrict__ XNH,
         __half* __restrict__ UH)
{
    const size_t bo = (size_t)blockIdx.z * PER_B;
    gemm1p<2>(SMH + bo, XNH + bo, 256.0f, nullptr, UH + bo);
}

__global__ void __launch_bounds__(256, 2)
out_kernel(const __half* __restrict__ WVTH, const __half* __restrict__ UH,
           float* __restrict__ outF)
{
    const size_t bo = (size_t)blockIdx.z * PER_B;
    gemm1p<0>(WVTH, UH + bo, 1.0f / 65536.0f, outF + bo, nullptr);
}

// ---------------------------------------------------------------------------
// Prep: z<16 -> x batch z: natural hi + transposed hi/lo (prescale 1).
//       z=16 wk natural x256 hi/lo; z=17 wq natural x256 hi/lo;
//       z=18 wv transposed x256 hi.
// ---------------------------------------------------------------------------
__global__ void __launch_bounds__(256)
prep_split(const float* __restrict__ x,
           const float* __restrict__ wk, const float* __restrict__ wq,
           const float* __restrict__ wv,
           __half* __restrict__ XTH, __half* __restrict__ XTL,
           __half* __restrict__ XNH,
           __half* __restrict__ WKNH, __half* __restrict__ WKNL,
           __half* __restrict__ WQNH, __half* __restrict__ WQNL,
           __half* __restrict__ WVTH)
{
    __shared__ float t[32][33];
    const int z = blockIdx.z;
    const int tx = threadIdx.x, ty = threadIdx.y;
    const int r0 = blockIdx.y * 32, c0 = blockIdx.x * 32;

    const float* in;
    float pres = 1.0f;
    bool natHi = false, natLo = false, trHi = false, trLo = false;
    __half *nh = nullptr, *nl = nullptr, *th = nullptr, *tl = nullptr;

    if (z < 16) {
        in = x + (size_t)z * PER_B;
        natHi = true; trHi = true; trLo = true;
        nh = XNH + (size_t)z * PER_B;
        th = XTH + (size_t)z * PER_B; tl = XTL + (size_t)z * PER_B;
    } else if (z == 16) {
        in = wk; pres = W_PRESCALE; natHi = true; natLo = true;
        nh = WKNH; nl = WKNL;
    } else if (z == 17) {
        in = wq; pres = W_PRESCALE; natHi = true; natLo = true;
        nh = WQNH; nl = WQNL;
    } else {
        in = wv; pres = W_PRESCALE; trHi = true;
        th = WVTH;
    }

    float v[4];
#pragma unroll
    for (int i = 0; i < 4; i++)
        v[i] = in[(size_t)(r0 + ty + i * 8) * L + c0 + tx] * pres;

    if (natHi) {
#pragma unroll
        for (int i = 0; i < 4; i++) {
            __half h = __float2half(v[i]);
            size_t o = (size_t)(r0 + ty + i * 8) * L + c0 + tx;
            nh[o] = h;
            if (natLo) nl[o] = __float2half(v[i] - __half2float(h));
        }
    }
    if (trHi) {
#pragma unroll
        for (int i = 0; i < 4; i++) t[ty + i * 8][tx] = v[i];
        __syncthreads();
#pragma unroll
        for (int i = 0; i < 4; i++) {
            float vv = t[tx][ty + i * 8];
            __half h = __float2half(vv);
            size_t o = (size_t)(c0 + ty + i * 8) * L + r0 + tx;
            th[o] = h;
            if (trLo) tl[o] = __float2half(vv - __half2float(h));
        }
    }
}

// ---------------------------------------------------------------------------
// row softmax (1024 wide), output single-digit fp16
// ---------------------------------------------------------------------------
__global__ void __launch_bounds__(256)
softmax_h(const float* __restrict__ kq, __half* __restrict__ oh)
{
    const size_t rb = (size_t)blockIdx.x * L;
    const int tid = threadIdx.x;
    float4 v = *reinterpret_cast<const float4*>(&kq[rb + tid * 4]);

    __shared__ float red[8];
    const int lane = tid & 31, wid = tid >> 5;

    float m = fmaxf(fmaxf(v.x, v.y), fmaxf(v.z, v.w));
#pragma unroll
    for (int o = 16; o; o >>= 1) m = fmaxf(m, __shfl_xor_sync(0xffffffffu, m, o));
    if (lane == 0) red[wid] = m;
    __syncthreads();
    m = red[0];
#pragma unroll
    for (int w = 1; w < 8; w++) m = fmaxf(m, red[w]);
    __syncthreads();

    v.x = expf(v.x - m); v.y = expf(v.y - m);
    v.z = expf(v.z - m); v.w = expf(v.w - m);
    float s = v.x + v.y + v.z + v.w;
#pragma unroll
    for (int o = 16; o; o >>= 1) s += __shfl_xor_sync(0xffffffffu, s, o);
    if (lane == 0) red[wid] = s;
    __syncthreads();
    s = red[0];
#pragma unroll
    for (int w = 1; w < 8; w++) s += red[w];

    const float inv = 1.0f / s;
    uint32_t p0 = (uint32_t)__half_as_ushort(__float2half(v.x * inv)) |
                  ((uint32_t)__half_as_ushort(__float2half(v.y * inv)) << 16);
    uint32_t p1 = (uint32_t)__half_as_ushort(__float2half(v.z * inv)) |
                  ((uint32_t)__half_as_ushort(__float2half(v.w * inv)) << 16);
    *reinterpret_cast<uint2*>(&oh[rb + tid * 4]) = make_uint2(p0, p1);
}

// ---------------------------------------------------------------------------
// host
// ---------------------------------------------------------------------------
extern "C" void kernel_launch(void* const* d_in, const int* in_sizes, int n_in,
                              void* d_out, int out_size)
{
    (void)in_sizes; (void)n_in; (void)out_size;
    const float* x  = (const float*)d_in[0];
    const float* wk = (const float*)d_in[1];
    const float* wq = (const float*)d_in[2];
    const float* wv = (const float*)d_in[3];
    float* out = (float*)d_out;

    void *xth, *xtl, *xnh, *tth, *ttl, *smh, *uh;
    void *gh, *gl, *wknh, *wknl, *wqnh, *wqnl, *wvth, *kq;
    cudaGetSymbolAddress(&xth, g_xT_hi);  cudaGetSymbolAddress(&xtl, g_xT_lo);
    cudaGetSymbolAddress(&xnh, g_xN_hi);
    cudaGetSymbolAddress(&tth, g_tT_hi);  cudaGetSymbolAddress(&ttl, g_tT_lo);
    cudaGetSymbolAddress(&smh, g_sm_hi);
    cudaGetSymbolAddress(&uh, g_u_hi);
    cudaGetSymbolAddress(&gh, g_G_hi);    cudaGetSymbolAddress(&gl, g_G_lo);
    cudaGetSymbolAddress(&wknh, g_wkN_hi); cudaGetSymbolAddress(&wknl, g_wkN_lo);
    cudaGetSymbolAddress(&wqnh, g_wqN_hi); cudaGetSymbolAddress(&wqnl, g_wqN_lo);
    cudaGetSymbolAddress(&wvth, g_wvT_hi);
    cudaGetSymbolAddress(&kq, g_kq);

    cudaFuncSetAttribute((const void*)g_kernel,
                         cudaFuncAttributeMaxDynamicSharedMemorySize, SMEM3);
    cudaFuncSetAttribute((const void*)t_kernel,
                         cudaFuncAttributeMaxDynamicSharedMemorySize, SMEM3);
    cudaFuncSetAttribute((const void*)kq_kernel,
                         cudaFuncAttributeMaxDynamicSharedMemorySize, SMEM3);
    cudaFuncSetAttribute((const void*)u_kernel,
                         cudaFuncAttributeMaxDynamicSharedMemorySize, SMEM1);
    cudaFuncSetAttribute((const void*)out_kernel,
                         cudaFuncAttributeMaxDynamicSharedMemorySize, SMEM1);

    // prep
    prep_split<<<dim3(32, 32, 19), dim3(32, 8)>>>(
        x, wk, wq, wv,
        (__half*)xth, (__half*)xtl, (__half*)xnh,
        (__half*)wknh, (__half*)wknl, (__half*)wqnh, (__half*)wqnl,
        (__half*)wvth);

    const dim3 g3(16, 8, BATCH);   // 3-pass: CTA 128x64
    const dim3 g1(8, 8, BATCH);    // 1-pass: CTA 128x128

    // G = wk.wq^T (unbatched)
    g_kernel<<<dim3(16, 8, 1), 256, SMEM3>>>(
        (__half*)wknh, (__half*)wknl, (__half*)wqnh, (__half*)wqnl,
        (__half*)gh, (__half*)gl);

    // tT = xT . G
    t_kernel<<<g3, 256, SMEM3>>>(
        (__half*)xth, (__half*)xtl, (__half*)gh, (__half*)gl,
        (__half*)tth, (__half*)ttl);

    // kq = xT . tT / 32
    kq_kernel<<<g3, 256, SMEM3>>>(
        (__half*)xth, (__half*)xtl, (__half*)tth, (__half*)ttl, (float*)kq);

    // softmax -> sm (1 digit)
    softmax_h<<<BATCH * L, 256>>>((const float*)kq, (__half*)smh);

    // u = sm . xN  (1-pass)
    u_kernel<<<g1, 256, SMEM1>>>((__half*)smh, (__half*)xnh, (__half*)uh);

    // out = wvT . u  (1-pass)
    out_kernel<<<g1, 256, SMEM1>>>((__half*)wvth, (__half*)uh, out);
}